// round 1
// baseline (speedup 1.0000x reference)
#include <cuda_runtime.h>
#include <math.h>

#define NSTATE 4096
#define LOUT   2048
#define NFFT   4096
#define NCHUNK 64
#define CLEN   64

struct Consts {
    double Q[2][2], Ux[2][2], Uo[2], Uu[2];
    double Ao[2][2], Bo[2], Do[2], Eo;
    double W0[2][2];  // ZGx @ Ux
    double RG;
};
__device__ Consts g_C;
__device__ double g_coef[4096][5];  // n0, n1, n2, tr, det per batch

// ---------------------------------------------------------------------------
// Setup: compute batch-independent circuit matrices from the alpha params.
// ---------------------------------------------------------------------------
__global__ void setup_kernel(const float* a_rg, const float* a_r1,
                             const float* a_c1, const float* a_c2) {
    const double T = 1.0 / 44100.0;
    // sigmoid in fp32 (matches reference), rest in fp64
    double sRG = (double)(1.f / (1.f + expf(-a_rg[0])));
    double sR1 = (double)(1.f / (1.f + expf(-a_r1[0])));
    double sC1 = (double)(1.f / (1.f + expf(-a_c1[0])));
    double sC2 = (double)(1.f / (1.f + expf(-a_c2[0])));
    double RG = (0.9 + 0.2 * sRG) * 1.0e6;
    double R1 = (0.99 + 0.02 * sR1) * 4.7e5;
    double C1 = (0.9 + 0.2 * sC1) * 3.3e-9;
    double C2 = (0.9 + 0.2 * sC2) * 1.0e-9;
    double Gr  = 1.0 / R1;
    double gx1 = 2.0 * C1 / T;
    double gx2 = 2.0 * C2 / T;

    // So = [[Nx^T Gx Nx + Nr^T Gr Nr, Nu^T], [Nu, 0]]
    double M[4][8];
    double So[4][4] = {
        { gx1,      -gx1,       0.0, 1.0},
        {-gx1,  gx1 + Gr,       0.0, 0.0},
        { 0.0,       0.0,       gx2, 0.0},
        { 1.0,       0.0,       0.0, 0.0}};
    for (int i = 0; i < 4; i++)
        for (int j = 0; j < 8; j++)
            M[i][j] = (j < 4) ? So[i][j] : ((j - 4 == i) ? 1.0 : 0.0);
    // Gauss-Jordan with partial pivot
    for (int col = 0; col < 4; col++) {
        int piv = col;
        for (int r = col + 1; r < 4; r++)
            if (fabs(M[r][col]) > fabs(M[piv][col])) piv = r;
        if (piv != col)
            for (int j = 0; j < 8; j++) { double t = M[col][j]; M[col][j] = M[piv][j]; M[piv][j] = t; }
        double inv = 1.0 / M[col][col];
        for (int j = 0; j < 8; j++) M[col][j] *= inv;
        for (int r = 0; r < 4; r++) {
            if (r == col) continue;
            double f = M[r][col];
            for (int j = 0; j < 8; j++) M[r][j] -= f * M[col][j];
        }
    }
    double Si[4][4];
    for (int i = 0; i < 4; i++)
        for (int j = 0; j < 4; j++) Si[i][j] = M[i][j + 4];

    // padded incidence rows (length 4)
    double vr[2][4] = {{0, 1, -1, 0}, {0, 0, 1, 0}};   // Nvp
    double xr[2][4] = {{1, -1, 0, 0}, {0, 0, 1, 0}};   // Nxp
    double orow[4]  = {0, 0, 1, 0};                    // Nop
    // Nup = e3

    auto qf = [&](const double* a, const double* b) {
        double s = 0.0;
        for (int i = 0; i < 4; i++)
            for (int j = 0; j < 4; j++) s += a[i] * Si[i][j] * b[j];
        return s;
    };
    Consts C;
    double gx[2] = {gx1, gx2};
    for (int i = 0; i < 2; i++)
        for (int j = 0; j < 2; j++) {
            C.Q[i][j]  = qf(vr[i], vr[j]);
            C.Ux[i][j] = qf(xr[i], vr[j]);
            double X   = qf(xr[i], xr[j]);
            C.Ao[i][j] = 2.0 * gx[i] * X - (i == j ? 1.0 : 0.0);
        }
    for (int j = 0; j < 2; j++) {
        C.Uo[j] = qf(orow, vr[j]);
        double uu = 0.0;
        for (int k = 0; k < 4; k++) uu += Si[3][k] * vr[j][k];
        C.Uu[j] = uu;
        C.Do[j] = qf(orow, xr[j]);
    }
    for (int i = 0; i < 2; i++) {
        double bi = 0.0;
        for (int k = 0; k < 4; k++) bi += xr[i][k] * Si[k][3];
        C.Bo[i] = 2.0 * gx[i] * bi;
        for (int j = 0; j < 2; j++) C.W0[i][j] = 2.0 * gx[i] * C.Ux[i][j];
    }
    C.Eo = Si[2][3];
    C.RG = RG;
    g_C = C;
}

// ---------------------------------------------------------------------------
// Per-batch biquad coefficients: n0, n1, n2 (num z^2,z,1) and tr, det (den).
// ---------------------------------------------------------------------------
__global__ void coeff_kernel(const float* __restrict__ cond,
                             const float* __restrict__ cw,
                             const float* __restrict__ cb, int B) {
    int b = blockIdx.x * blockDim.x + threadIdx.x;
    if (b >= B) return;
    float zf  = cond[b] * cw[0] + cb[0];
    float pot = 1.f / (1.f + expf(-zf));
    float pf  = (powf(10.f, pot) - 1.f) / 9.f;
    pf = fminf(fmaxf(pf, 1e-4f), 1.f - 1e-4f);
    double p = (double)pf;

    const Consts C = g_C;
    double d0 = (1.0 - p) * C.RG, d1 = p * C.RG;
    double r00 = d0 + C.Q[0][0], r01 = C.Q[0][1];
    double r10 = C.Q[1][0],      r11 = d1 + C.Q[1][1];
    double id  = 1.0 / (r00 * r11 - r01 * r10);
    double S00 = r11 * id, S01 = -r01 * id, S10 = -r10 * id, S11 = r00 * id;

    double W[2][2];
    for (int i = 0; i < 2; i++) {
        W[i][0] = C.W0[i][0] * S00 + C.W0[i][1] * S10;
        W[i][1] = C.W0[i][0] * S01 + C.W0[i][1] * S11;
    }
    double A[2][2], Bm[2];
    for (int i = 0; i < 2; i++) {
        for (int j = 0; j < 2; j++)
            A[i][j] = C.Ao[i][j] - (W[i][0] * C.Ux[j][0] + W[i][1] * C.Ux[j][1]);
        Bm[i] = C.Bo[i] - (W[i][0] * C.Uu[0] + W[i][1] * C.Uu[1]);
    }
    double V0 = C.Uo[0] * S00 + C.Uo[1] * S10;
    double V1 = C.Uo[0] * S01 + C.Uo[1] * S11;
    double Dm[2];
    for (int j = 0; j < 2; j++)
        Dm[j] = C.Do[j] - (V0 * C.Ux[j][0] + V1 * C.Ux[j][1]);
    double Em = C.Eo - (V0 * C.Uu[0] + V1 * C.Uu[1]);

    double tr  = A[0][0] + A[1][1];
    double det = A[0][0] * A[1][1] - A[0][1] * A[1][0];
    double E00 = A[0][0] - Bm[0] * Dm[0], E01 = A[0][1] - Bm[0] * Dm[1];
    double E10 = A[1][0] - Bm[1] * Dm[0], E11 = A[1][1] - Bm[1] * Dm[1];
    double trE = E00 + E11, detE = E00 * E11 - E01 * E10;

    g_coef[b][0] = Em;                           // n0 (coef of z^2)
    g_coef[b][1] = -trE - (Em - 1.0) * tr;       // n1
    g_coef[b][2] = detE + (Em - 1.0) * det;      // n2
    g_coef[b][3] = tr;
    g_coef[b][4] = det;
}

// ---------------------------------------------------------------------------
// Circular backward biquad via chunk-affine decomposition (exact periodic).
// st[0:2048) = state[b, 2048:4096); st[2048:4096) = x[b, 0:2048).
// y[n] = s[n] + tr*y[n+1] - det*y[n+2],  s[n] = n0*st[n] + n1*st[n+1] + n2*st[n+2]
// out[b, i] = y[2048 + i].
// ---------------------------------------------------------------------------
__global__ void __launch_bounds__(256, 1)
filter_kernel(const float* __restrict__ x, const float* __restrict__ state,
              float* __restrict__ out, int B) {
    __shared__ double s_s[NFFT + NCHUNK];        // padded: idx = n + (n>>6)
    __shared__ float  yout[LOUT + LOUT / CLEN];  // padded: idx = i + (i>>6)
    __shared__ double Mv[NCHUNK][4];
    __shared__ double Pv[NCHUNK][2];
    __shared__ double vin[NCHUNK][2];

    int b   = blockIdx.x;
    int tid = threadIdx.x;
    double n0 = g_coef[b][0], n1 = g_coef[b][1], n2 = g_coef[b][2];
    double tr = g_coef[b][3], dt = g_coef[b][4];

    const float* stt = state + (size_t)b * NSTATE + LOUT;  // state tail
    const float* xb  = x + (size_t)b * LOUT;

    // Phase A: source term s[n] into padded shared
    for (int n = tid; n < NFFT; n += 256) {
        int i1 = (n + 1) & (NFFT - 1), i2 = (n + 2) & (NFFT - 1);
        double v0 = (n  < LOUT) ? (double)stt[n]  : (double)xb[n - LOUT];
        double v1 = (i1 < LOUT) ? (double)stt[i1] : (double)xb[i1 - LOUT];
        double v2 = (i2 < LOUT) ? (double)stt[i2] : (double)xb[i2 - LOUT];
        s_s[n + (n >> 6)] = n0 * v0 + n1 * v1 + n2 * v2;
    }
    __syncthreads();

    // Phase B: per-chunk affine map (M = T^64, P = particular solution)
    if (tid < NCHUNK) {
        int c = tid;
        int n = NFFT - 1 - CLEN * c;
        double pa = 0.0, pb = 0.0;
        double ma0 = 1.0, ma1 = 0.0, mb0 = 0.0, mb1 = 1.0;
#pragma unroll 4
        for (int i = 0; i < CLEN; i++, n--) {
            double s  = s_s[n + (n >> 6)];
            double pc = fma(tr, pa, fma(-dt, pb, s));
            double m0 = fma(tr, ma0, -dt * mb0);
            double m1 = fma(tr, ma1, -dt * mb1);
            pb = pa; pa = pc;
            mb0 = ma0; mb1 = ma1; ma0 = m0; ma1 = m1;
        }
        Mv[c][0] = ma0; Mv[c][1] = ma1; Mv[c][2] = mb0; Mv[c][3] = mb1;
        Pv[c][0] = pa;  Pv[c][1] = pb;
    }
    __syncthreads();

    // Phase C: sequential composition + periodic fixed point (thread 0)
    if (tid == 0) {
        double F00 = 1, F01 = 0, F10 = 0, F11 = 1, P0 = 0, P1 = 0;
        for (int c = 0; c < NCHUNK; c++) {
            double m00 = Mv[c][0], m01 = Mv[c][1], m10 = Mv[c][2], m11 = Mv[c][3];
            double q0 = Pv[c][0], q1 = Pv[c][1];
            double np0 = m00 * P0 + m01 * P1 + q0;
            double np1 = m10 * P0 + m11 * P1 + q1;
            double f00 = m00 * F00 + m01 * F10, f01 = m00 * F01 + m01 * F11;
            double f10 = m10 * F00 + m11 * F10, f11 = m10 * F01 + m11 * F11;
            P0 = np0; P1 = np1; F00 = f00; F01 = f01; F10 = f10; F11 = f11;
        }
        // periodic BC: v = F v + P  ->  (I - F) v = P
        double a = 1.0 - F00, bb = -F01, cc = -F10, dd = 1.0 - F11;
        double idn = 1.0 / (a * dd - bb * cc);
        double v0 = (dd * P0 - bb * P1) * idn;
        double v1 = (-cc * P0 + a * P1) * idn;
        vin[0][0] = v0; vin[0][1] = v1;
        for (int c = 1; c < NCHUNK; c++) {
            double w0 = Mv[c - 1][0] * v0 + Mv[c - 1][1] * v1 + Pv[c - 1][0];
            double w1 = Mv[c - 1][2] * v0 + Mv[c - 1][3] * v1 + Pv[c - 1][1];
            vin[c][0] = w0; vin[c][1] = w1;
            v0 = w0; v1 = w1;
        }
    }
    __syncthreads();

    // Phase D: replay the 32 chunks covering n in [2048, 4096) with exact ICs
    if (tid < 32) {
        int c = tid;
        int n = NFFT - 1 - CLEN * c;
        double pa = vin[c][0], pb = vin[c][1];
#pragma unroll 4
        for (int i = 0; i < CLEN; i++, n--) {
            double s  = s_s[n + (n >> 6)];
            double yc = fma(tr, pa, fma(-dt, pb, s));
            int k = n - LOUT;
            yout[k + (k >> 6)] = (float)yc;
            pb = pa; pa = yc;
        }
    }
    __syncthreads();

    // Phase E: coalesced writeback
    float* ob = out + (size_t)b * LOUT;
    for (int i = tid; i < LOUT; i += 256) ob[i] = yout[i + (i >> 6)];
}

extern "C" void kernel_launch(void* const* d_in, const int* in_sizes, int n_in,
                              void* d_out, int out_size) {
    const float* x     = (const float*)d_in[0];
    const float* cond  = (const float*)d_in[1];
    const float* state = (const float*)d_in[2];
    const float* a_rg  = (const float*)d_in[3];
    const float* a_r1  = (const float*)d_in[4];
    const float* a_c1  = (const float*)d_in[5];
    const float* a_c2  = (const float*)d_in[6];
    const float* cw    = (const float*)d_in[7];
    const float* cb    = (const float*)d_in[8];

    int B = in_sizes[1];  // cond is [B, 1]
    if (B > 4096) B = 4096;

    setup_kernel<<<1, 1>>>(a_rg, a_r1, a_c1, a_c2);
    coeff_kernel<<<(B + 255) / 256, 256>>>(cond, cw, cb, B);
    filter_kernel<<<B, 256>>>(x, state, (float*)d_out, B);
}